// round 1
// baseline (speedup 1.0000x reference)
#include <cuda_runtime.h>
#include <math.h>

// Shapes (fixed for this problem)
#define MT 8192   // B*T rows
#define DD 1024   // in_features (K of first GEMM)
#define NB 8192   // n_bank (N of first GEMM, K of second)
#define DO 1024   // out_features

// 256 MB scratch for the score matrix + per-row scale. Static __device__
// globals are the allowed scratch mechanism (no allocations anywhere).
__device__ float g_S[67108864];   // 8192*8192
__device__ float g_scale[8192];

__device__ __forceinline__ float gelu_exact(float x) {
    // exact (erf) GELU, matching jax approximate=False
    return 0.5f * x * (1.0f + erff(x * 0.70710678118654752f));
}

// ---------------------------------------------------------------------------
// Kernel 1: S = Q (8192x1024, row-major) * K^T (K is 8192x1024 row-major)
// 128x128 tile, BK=8, 256 threads, 8x8 per-thread microtile.
// ---------------------------------------------------------------------------
__global__ __launch_bounds__(256, 2)
void score_gemm_nt(const float* __restrict__ Q, const float* __restrict__ Kb) {
    __shared__ float As[8][128];
    __shared__ float Bs[8][128];
    const int tid = threadIdx.x;
    const int m0 = blockIdx.y * 128;
    const int n0 = blockIdx.x * 128;

    // global-load mapping: each thread loads one float4 per operand per k-tile
    const int lr = tid >> 1;          // 0..127 row within tile
    const int lc = (tid & 1) << 2;    // 0 or 4 (k offset)
    const float* aP = Q  + (size_t)(m0 + lr) * DD + lc;
    const float* bP = Kb + (size_t)(n0 + lr) * DD + lc;

    // compute mapping
    const int tx = (tid & 15) << 3;   // col fragment base (0..120)
    const int ty = (tid >> 4) << 3;   // row fragment base (0..120)

    float acc[8][8];
#pragma unroll
    for (int i = 0; i < 8; ++i)
#pragma unroll
        for (int j = 0; j < 8; ++j) acc[i][j] = 0.0f;

    for (int k0 = 0; k0 < DD; k0 += 8) {
        const float4 av = *(const float4*)(aP + k0);
        const float4 bv = *(const float4*)(bP + k0);
        __syncthreads();
        As[lc + 0][lr] = av.x; As[lc + 1][lr] = av.y;
        As[lc + 2][lr] = av.z; As[lc + 3][lr] = av.w;
        Bs[lc + 0][lr] = bv.x; Bs[lc + 1][lr] = bv.y;
        Bs[lc + 2][lr] = bv.z; Bs[lc + 3][lr] = bv.w;
        __syncthreads();
#pragma unroll
        for (int kk = 0; kk < 8; ++kk) {
            float a[8], b[8];
            const float4 a0 = *(const float4*)&As[kk][ty];
            const float4 a1 = *(const float4*)&As[kk][ty + 4];
            const float4 b0 = *(const float4*)&Bs[kk][tx];
            const float4 b1 = *(const float4*)&Bs[kk][tx + 4];
            a[0]=a0.x; a[1]=a0.y; a[2]=a0.z; a[3]=a0.w;
            a[4]=a1.x; a[5]=a1.y; a[6]=a1.z; a[7]=a1.w;
            b[0]=b0.x; b[1]=b0.y; b[2]=b0.z; b[3]=b0.w;
            b[4]=b1.x; b[5]=b1.y; b[6]=b1.z; b[7]=b1.w;
#pragma unroll
            for (int i = 0; i < 8; ++i)
#pragma unroll
                for (int j = 0; j < 8; ++j)
                    acc[i][j] = fmaf(a[i], b[j], acc[i][j]);
        }
    }

#pragma unroll
    for (int i = 0; i < 8; ++i) {
        float* p = g_S + (size_t)(m0 + ty + i) * NB + n0 + tx;
        *(float4*)(p)     = make_float4(acc[i][0], acc[i][1], acc[i][2], acc[i][3]);
        *(float4*)(p + 4) = make_float4(acc[i][4], acc[i][5], acc[i][6], acc[i][7]);
    }
}

// ---------------------------------------------------------------------------
// Kernel 2: per-row scale = sqrt(NB) / ||S_row||_2
// ---------------------------------------------------------------------------
__global__ __launch_bounds__(256)
void row_scale_kernel() {
    const int row = blockIdx.x;
    const float4* p = (const float4*)(g_S + (size_t)row * NB);
    float s = 0.0f;
    for (int i = threadIdx.x; i < NB / 4; i += 256) {
        const float4 v = p[i];
        s += v.x * v.x + v.y * v.y + v.z * v.z + v.w * v.w;
    }
    __shared__ float red[256];
    red[threadIdx.x] = s;
    __syncthreads();
    for (int o = 128; o > 0; o >>= 1) {
        if (threadIdx.x < o) red[threadIdx.x] += red[threadIdx.x + o];
        __syncthreads();
    }
    if (threadIdx.x == 0)
        g_scale[row] = sqrtf((float)NB) / sqrtf(red[0]);
}

// ---------------------------------------------------------------------------
// Kernel 3: O = gelu(scale[m] * S) * V   (NN GEMM, gelu fused into A load)
// A = S (8192x8192), B = V (8192x1024), 128x128 tile, BK=8.
// ---------------------------------------------------------------------------
__global__ __launch_bounds__(256, 2)
void out_gemm_nn(const float* __restrict__ V, float* __restrict__ O) {
    __shared__ float As[8][128];
    __shared__ float Bs[8][128];
    const int tid = threadIdx.x;
    const int n0 = blockIdx.x * 128;   // x fastest -> the 8 col-tiles of one
    const int m0 = blockIdx.y * 128;   // row-block run together (L2 reuse of S)

    const int lr = tid >> 1;
    const int lc = (tid & 1) << 2;
    const float rs = g_scale[m0 + lr];
    const float* aP = g_S + (size_t)(m0 + lr) * NB + lc;

    const int bkr = tid >> 5;            // 0..7  (k row within B tile)
    const int bkc = (tid & 31) << 2;     // 0..124 (col within B tile)

    const int tx = (tid & 15) << 3;
    const int ty = (tid >> 4) << 3;

    float acc[8][8];
#pragma unroll
    for (int i = 0; i < 8; ++i)
#pragma unroll
        for (int j = 0; j < 8; ++j) acc[i][j] = 0.0f;

    for (int k0 = 0; k0 < NB; k0 += 8) {
        float4 av = *(const float4*)(aP + k0);
        const float4 bv = *(const float4*)(V + (size_t)(k0 + bkr) * DO + n0 + bkc);
        // fused gating: gelu(score * sqrtN / norm)
        av.x = gelu_exact(av.x * rs);
        av.y = gelu_exact(av.y * rs);
        av.z = gelu_exact(av.z * rs);
        av.w = gelu_exact(av.w * rs);
        __syncthreads();
        As[lc + 0][lr] = av.x; As[lc + 1][lr] = av.y;
        As[lc + 2][lr] = av.z; As[lc + 3][lr] = av.w;
        *(float4*)&Bs[bkr][bkc] = bv;
        __syncthreads();
#pragma unroll
        for (int kk = 0; kk < 8; ++kk) {
            float a[8], b[8];
            const float4 a0 = *(const float4*)&As[kk][ty];
            const float4 a1 = *(const float4*)&As[kk][ty + 4];
            const float4 b0 = *(const float4*)&Bs[kk][tx];
            const float4 b1 = *(const float4*)&Bs[kk][tx + 4];
            a[0]=a0.x; a[1]=a0.y; a[2]=a0.z; a[3]=a0.w;
            a[4]=a1.x; a[5]=a1.y; a[6]=a1.z; a[7]=a1.w;
            b[0]=b0.x; b[1]=b0.y; b[2]=b0.z; b[3]=b0.w;
            b[4]=b1.x; b[5]=b1.y; b[6]=b1.z; b[7]=b1.w;
#pragma unroll
            for (int i = 0; i < 8; ++i)
#pragma unroll
                for (int j = 0; j < 8; ++j)
                    acc[i][j] = fmaf(a[i], b[j], acc[i][j]);
        }
    }

#pragma unroll
    for (int i = 0; i < 8; ++i) {
        float* p = O + (size_t)(m0 + ty + i) * DO + n0 + tx;
        *(float4*)(p)     = make_float4(acc[i][0], acc[i][1], acc[i][2], acc[i][3]);
        *(float4*)(p + 4) = make_float4(acc[i][4], acc[i][5], acc[i][6], acc[i][7]);
    }
}

// ---------------------------------------------------------------------------
extern "C" void kernel_launch(void* const* d_in, const int* in_sizes, int n_in,
                              void* d_out, int out_size) {
    const float* q = (const float*)d_in[0];  // [4,2048,1024]
    const float* k = (const float*)d_in[1];  // [8192,1024]
    const float* v = (const float*)d_in[2];  // [8192,1024]
    float* o = (float*)d_out;                // [4,2048,1024] fp32

    score_gemm_nt<<<dim3(NB / 128, MT / 128), 256>>>(q, k);
    row_scale_kernel<<<MT, 256>>>();
    out_gemm_nn<<<dim3(DO / 128, MT / 128), 256>>>(v, o);
}

// round 6
// speedup vs baseline: 2.9051x; 2.9051x over previous
#include <cuda_runtime.h>
#include <cuda_bf16.h>
#include <math.h>

#define MT 8192   // B*T rows
#define DD 1024   // in_features
#define NB 8192   // n_bank
#define DO 1024   // out_features

typedef __nv_bfloat16 bf16;

// ---------------- static device scratch (no allocations allowed) -----------
// NOTE: these symbols must ONLY be referenced from device code. Passing them
// as kernel arguments from host code passes the HOST shadow address (which
// GB300 ATS happily dereferences as host memory -> silent zeros). That was
// the bug in rounds 3-5.
__device__ __align__(128) bf16 g_Qhi[MT * DD];
__device__ __align__(128) bf16 g_Qlo[MT * DD];
__device__ __align__(128) bf16 g_Khi[NB * DD];
__device__ __align__(128) bf16 g_Klo[NB * DD];
__device__ __align__(128) bf16 g_Vthi[DO * NB];        // V^T [DO][NB]
__device__ __align__(128) bf16 g_Vtlo[DO * NB];
__device__ __align__(128) float g_S[(size_t)MT * NB];  // fp32 scores
__device__ __align__(128) bf16 g_Ghi[(size_t)MT * NB]; // gated hi
__device__ __align__(128) bf16 g_Glo[(size_t)MT * NB]; // gated lo
__device__ float g_sumsq[MT];
__device__ float g_scale[MT];

// ---------------- helpers ---------------------------------------------------
__device__ __forceinline__ unsigned smem_u32(const void* p) {
    unsigned a;
    asm("{ .reg .u64 t; cvta.to.shared.u64 t, %1; cvt.u32.u64 %0, t; }"
        : "=r"(a) : "l"(p));
    return a;
}
#define CPA16(d, s) \
    asm volatile("cp.async.cg.shared.global [%0], [%1], 16;" :: "r"(d), "l"(s) : "memory")
#define CPCOMMIT() asm volatile("cp.async.commit_group;" ::: "memory")
#define CPWAIT1()  asm volatile("cp.async.wait_group 1;" ::: "memory")

#define LDSM4(r0, r1, r2, r3, a) \
    asm volatile("ldmatrix.sync.aligned.m8n8.x4.shared.b16 {%0,%1,%2,%3}, [%4];" \
        : "=r"(r0), "=r"(r1), "=r"(r2), "=r"(r3) : "r"(a))
#define LDSM2(r0, r1, a) \
    asm volatile("ldmatrix.sync.aligned.m8n8.x2.shared.b16 {%0,%1}, [%2];" \
        : "=r"(r0), "=r"(r1) : "r"(a))
#define MMA(c, a, b) \
    asm volatile("mma.sync.aligned.m16n8k16.row.col.f32.bf16.bf16.f32 " \
        "{%0,%1,%2,%3},{%4,%5,%6,%7},{%8,%9},{%0,%1,%2,%3};" \
        : "+f"((c)[0]), "+f"((c)[1]), "+f"((c)[2]), "+f"((c)[3]) \
        : "r"((a)[0]), "r"((a)[1]), "r"((a)[2]), "r"((a)[3]), \
          "r"((b)[0]), "r"((b)[1]))

// smem tile: 128 rows x 16 cols bf16, 32B rows, XOR-swizzled 16B segments.
// byte offset of (row, seg) = row*32 + ((seg ^ ((row>>2)&1)) * 16)
// -> any 8 consecutive rows hit 8 distinct 16B offsets mod 128 (no LDSM conflicts)
#define TILE_B   4096               // 128*32
#define STAGE_B  16384              // Ahi,Alo,Bhi,Blo
// total static shared: 2 * 16384 = 32768 bytes

__device__ __forceinline__ unsigned sw_off(int row, int seg) {
    return (unsigned)(row * 32 + ((seg ^ ((row >> 2) & 1)) << 4));
}

__device__ __forceinline__ void load_tile(unsigned sm, const bf16* g, int ld,
                                          int k0, int tid) {
    int row = tid >> 1, seg = tid & 1;
    CPA16(sm + sw_off(row, seg), g + (size_t)row * ld + k0 + seg * 8);
}

// ---------------------------------------------------------------------------
// Fused split-bf16 GEMM: D = (Ahi+Alo)*(Bhi+Blo)^T (lo*lo dropped)
// CTA 128x128, K-chunk 16, 2-stage cp.async double buffer, 8 warps (2m x 4n).
// EPI1: A=Qhi/Qlo, B=Khi/Klo, write fp32 g_S + row sumsq atomics.
// else: A=Ghi/Glo, B=Vthi/Vtlo, write fp32 Out.
// Operand arrays are selected INSIDE device code (template flag) — never
// passed from host.
// ---------------------------------------------------------------------------
template<int NC, int LDA, int LDB, bool EPI1>
__global__ __launch_bounds__(256) void gemm_kernel(float* __restrict__ Out,
                                                   int ldo) {
    const bf16* __restrict__ Ahi = EPI1 ? g_Qhi : g_Ghi;
    const bf16* __restrict__ Alo = EPI1 ? g_Qlo : g_Glo;
    const bf16* __restrict__ Bhi = EPI1 ? g_Khi : g_Vthi;
    const bf16* __restrict__ Blo = EPI1 ? g_Klo : g_Vtlo;

    __shared__ __align__(128) char dsm[2 * STAGE_B];   // 32768 bytes
    const unsigned sbase = smem_u32(dsm);
    const int tid = threadIdx.x, lane = tid & 31, wid = tid >> 5;
    const int wm = wid >> 2, wn = wid & 3;
    const int m0 = blockIdx.y * 128, n0 = blockIdx.x * 128;

    const bf16* pAhi = Ahi + (size_t)m0 * LDA;
    const bf16* pAlo = Alo + (size_t)m0 * LDA;
    const bf16* pBhi = Bhi + (size_t)n0 * LDB;
    const bf16* pBlo = Blo + (size_t)n0 * LDB;

    float acc[4][4][4];
#pragma unroll
    for (int f = 0; f < 4; ++f)
#pragma unroll
        for (int g = 0; g < 4; ++g)
#pragma unroll
            for (int j = 0; j < 4; ++j) acc[f][g][j] = 0.f;

    // prologue: stages 0,1 <- chunks 0,1
#pragma unroll
    for (int s = 0; s < 2; ++s) {
        unsigned sb = sbase + s * STAGE_B;
        int k0 = s * 16;
        load_tile(sb,              pAhi, LDA, k0, tid);
        load_tile(sb + TILE_B,     pAlo, LDA, k0, tid);
        load_tile(sb + 2 * TILE_B, pBhi, LDB, k0, tid);
        load_tile(sb + 3 * TILE_B, pBlo, LDB, k0, tid);
        CPCOMMIT();
    }

    // ldmatrix lane addressing (K=16: exactly one k-step per chunk)
    const int ra = lane & 15, sa = lane >> 4;            // A x4: rows 0-15, seg
    const int rb = lane & 7,  sbseg = (lane >> 3) & 1;   // B x2: rows 0-7, seg

    for (int c = 0; c < NC; ++c) {
        CPWAIT1();                       // chunk c resident (this thread)
        __syncthreads();                 // all threads' chunk-c data visible
        unsigned sb = sbase + (c & 1) * STAGE_B;
        unsigned ah[4][4], al[4][4], bh[4][2], bl[4][2];
#pragma unroll
        for (int f = 0; f < 4; ++f) {
            unsigned ad = sb + sw_off(wm * 64 + f * 16 + ra, sa);
            LDSM4(ah[f][0], ah[f][1], ah[f][2], ah[f][3], ad);
            LDSM4(al[f][0], al[f][1], al[f][2], al[f][3], ad + TILE_B);
        }
#pragma unroll
        for (int g = 0; g < 4; ++g) {
            unsigned bd = sb + 2 * TILE_B + sw_off(wn * 32 + g * 8 + rb, sbseg);
            LDSM2(bh[g][0], bh[g][1], bd);
            LDSM2(bl[g][0], bl[g][1], bd + TILE_B);
        }
#pragma unroll
        for (int f = 0; f < 4; ++f)
#pragma unroll
            for (int g = 0; g < 4; ++g) {
                MMA(acc[f][g], ah[f], bh[g]);
                MMA(acc[f][g], al[f], bh[g]);
                MMA(acc[f][g], ah[f], bl[g]);
            }
        __syncthreads();                 // all warps done reading buffer c&1
        if (c + 2 < NC) {
            unsigned sn = sbase + (c & 1) * STAGE_B;
            int k0 = (c + 2) * 16;
            load_tile(sn,              pAhi, LDA, k0, tid);
            load_tile(sn + TILE_B,     pAlo, LDA, k0, tid);
            load_tile(sn + 2 * TILE_B, pBhi, LDB, k0, tid);
            load_tile(sn + 3 * TILE_B, pBlo, LDB, k0, tid);
        }
        CPCOMMIT();
    }

    // epilogue
    const int mrb = m0 + wm * 64 + (lane >> 2);
    const int ncb = n0 + wn * 32 + (lane & 3) * 2;
#pragma unroll
    for (int f = 0; f < 4; ++f) {
        const int r0 = mrb + f * 16;
        float s0 = 0.f, s1 = 0.f;
#pragma unroll
        for (int g = 0; g < 4; ++g) {
            const int cc = ncb + g * 8;
            if (EPI1) {
                *(float2*)&g_S[(size_t)r0 * NB + cc] =
                    make_float2(acc[f][g][0], acc[f][g][1]);
                *(float2*)&g_S[(size_t)(r0 + 8) * NB + cc] =
                    make_float2(acc[f][g][2], acc[f][g][3]);
                s0 += acc[f][g][0] * acc[f][g][0] + acc[f][g][1] * acc[f][g][1];
                s1 += acc[f][g][2] * acc[f][g][2] + acc[f][g][3] * acc[f][g][3];
            } else {
                *(float2*)&Out[(size_t)r0 * ldo + cc] =
                    make_float2(acc[f][g][0], acc[f][g][1]);
                *(float2*)&Out[(size_t)(r0 + 8) * ldo + cc] =
                    make_float2(acc[f][g][2], acc[f][g][3]);
            }
        }
        if (EPI1) {
            s0 += __shfl_xor_sync(0xffffffff, s0, 1);
            s0 += __shfl_xor_sync(0xffffffff, s0, 2);
            s1 += __shfl_xor_sync(0xffffffff, s1, 1);
            s1 += __shfl_xor_sync(0xffffffff, s1, 2);
            if ((lane & 3) == 0) {
                atomicAdd(&g_sumsq[r0], s0);
                atomicAdd(&g_sumsq[r0 + 8], s1);
            }
        }
    }
}

// ---------------- elementwise kernels --------------------------------------
__device__ __forceinline__ void split4(const float4 v, uint2& H, uint2& L) {
    union { unsigned short s[4]; uint2 u; } h, l;
    const float f[4] = {v.x, v.y, v.z, v.w};
#pragma unroll
    for (int j = 0; j < 4; ++j) {
        bf16 hb = __float2bfloat16(f[j]);
        h.s[j] = __bfloat16_as_ushort(hb);
        l.s[j] = __bfloat16_as_ushort(__float2bfloat16(f[j] - __bfloat162float(hb)));
    }
    H = h.u; L = l.u;
}

__global__ __launch_bounds__(256) void splitQK_kernel(const float* __restrict__ q,
                                                      const float* __restrict__ k) {
    size_t i = (size_t)blockIdx.x * 256 + threadIdx.x;    // over MT*DD/4
    uint2 H, L;
    split4(((const float4*)q)[i], H, L);
    ((uint2*)g_Qhi)[i] = H; ((uint2*)g_Qlo)[i] = L;
    split4(((const float4*)k)[i], H, L);
    ((uint2*)g_Khi)[i] = H; ((uint2*)g_Klo)[i] = L;
}

__global__ void vtrans_kernel(const float* __restrict__ V) {
    __shared__ float t[32][33];
    const int o0 = blockIdx.x * 32, n0 = blockIdx.y * 32;
    const int tx = threadIdx.x, ty = threadIdx.y;
    for (int r = ty; r < 32; r += 8)
        t[r][tx] = V[(size_t)(n0 + r) * DO + o0 + tx];
    __syncthreads();
    for (int r = ty; r < 32; r += 8) {
        float f = t[tx][r];
        size_t idx = (size_t)(o0 + r) * NB + n0 + tx;
        bf16 h = __float2bfloat16(f);
        g_Vthi[idx] = h;
        g_Vtlo[idx] = __float2bfloat16(f - __bfloat162float(h));
    }
}

__global__ void zero_sumsq_kernel() {
    int i = blockIdx.x * 256 + threadIdx.x;
    if (i < MT) g_sumsq[i] = 0.f;
}
__global__ void row_scale_kernel2() {
    int i = blockIdx.x * 256 + threadIdx.x;
    if (i < MT) g_scale[i] = 90.50966799187809f / sqrtf(g_sumsq[i]);
}

__global__ __launch_bounds__(256) void gating_kernel() {
    size_t i = (size_t)blockIdx.x * 256 + threadIdx.x;    // over MT*NB/8
    size_t off = i * 8;
    const float sc = g_scale[off >> 13];
    float4 v0 = *(const float4*)(g_S + off);
    float4 v1 = *(const float4*)(g_S + off + 4);
    float f[8] = {v0.x, v0.y, v0.z, v0.w, v1.x, v1.y, v1.z, v1.w};
    union { unsigned short s[8]; uint4 v; } OH, OL;
#pragma unroll
    for (int j = 0; j < 8; ++j) {
        float x = f[j] * sc;
        float g = 0.5f * x * (1.0f + erff(x * 0.70710678118654752f));
        bf16 h = __float2bfloat16(g);
        OH.s[j] = __bfloat16_as_ushort(h);
        OL.s[j] = __bfloat16_as_ushort(__float2bfloat16(g - __bfloat162float(h)));
    }
    *(uint4*)(g_Ghi + off) = OH.v;
    *(uint4*)(g_Glo + off) = OL.v;
}

// ---------------------------------------------------------------------------
extern "C" void kernel_launch(void* const* d_in, const int* in_sizes, int n_in,
                              void* d_out, int out_size) {
    const float* q = (const float*)d_in[0];
    const float* k = (const float*)d_in[1];
    const float* v = (const float*)d_in[2];
    float* o = (float*)d_out;

    splitQK_kernel<<<(MT * DD / 4) / 256, 256>>>(q, k);
    vtrans_kernel<<<dim3(DO / 32, NB / 32), dim3(32, 8)>>>(v);
    zero_sumsq_kernel<<<MT / 256, 256>>>();
    gemm_kernel<DD / 16, DD, DD, true><<<dim3(NB / 128, MT / 128), 256>>>(
        nullptr, NB);
    row_scale_kernel2<<<MT / 256, 256>>>();
    gating_kernel<<<(int)((size_t)MT * NB / 8 / 256), 256>>>();
    gemm_kernel<NB / 16, NB, NB, false><<<dim3(DO / 128, MT / 128), 256>>>(
        o, DO);
}

// round 8
// speedup vs baseline: 3.0668x; 1.0556x over previous
#include <cuda_runtime.h>
#include <cuda_bf16.h>
#include <math.h>

#define MT 8192   // B*T rows
#define DD 1024   // in_features
#define NB 8192   // n_bank
#define DO 1024   // out_features

typedef __nv_bfloat16 bf16;

// ---------------- static device scratch (no allocations allowed) -----------
// NOTE: referenced ONLY from device code (host shadow-address trap).
__device__ __align__(128) bf16 g_Qhi[MT * DD];
__device__ __align__(128) bf16 g_Qlo[MT * DD];
__device__ __align__(128) bf16 g_Khi[NB * DD];
__device__ __align__(128) bf16 g_Klo[NB * DD];
__device__ __align__(128) bf16 g_Vthi[DO * NB];        // V^T [DO][NB]
__device__ __align__(128) bf16 g_Vtlo[DO * NB];
__device__ __align__(128) float g_S[(size_t)MT * NB];  // fp32 scores
__device__ __align__(128) bf16 g_Ghi[(size_t)MT * NB]; // gated hi
__device__ __align__(128) bf16 g_Glo[(size_t)MT * NB]; // gated lo
__device__ float g_sumsq[MT];
__device__ float g_scale[MT];

// ---------------- helpers ---------------------------------------------------
__device__ __forceinline__ unsigned smem_u32(const void* p) {
    unsigned a;
    asm("{ .reg .u64 t; cvta.to.shared.u64 t, %1; cvt.u32.u64 %0, t; }"
        : "=r"(a) : "l"(p));
    return a;
}
#define CPA16(d, s) \
    asm volatile("cp.async.cg.shared.global [%0], [%1], 16;" :: "r"(d), "l"(s) : "memory")
#define CPCOMMIT() asm volatile("cp.async.commit_group;" ::: "memory")
#define CPWAIT1()  asm volatile("cp.async.wait_group 1;" ::: "memory")

#define LDSM4(r0, r1, r2, r3, a) \
    asm volatile("ldmatrix.sync.aligned.m8n8.x4.shared.b16 {%0,%1,%2,%3}, [%4];" \
        : "=r"(r0), "=r"(r1), "=r"(r2), "=r"(r3) : "r"(a))
#define LDSM2(r0, r1, a) \
    asm volatile("ldmatrix.sync.aligned.m8n8.x2.shared.b16 {%0,%1}, [%2];" \
        : "=r"(r0), "=r"(r1) : "r"(a))
#define MMA(c, a, b) \
    asm volatile("mma.sync.aligned.m16n8k16.row.col.f32.bf16.bf16.f32 " \
        "{%0,%1,%2,%3},{%4,%5,%6,%7},{%8,%9},{%0,%1,%2,%3};" \
        : "+f"((c)[0]), "+f"((c)[1]), "+f"((c)[2]), "+f"((c)[3]) \
        : "r"((a)[0]), "r"((a)[1]), "r"((a)[2]), "r"((a)[3]), \
          "r"((b)[0]), "r"((b)[1]))

// smem tile: 128 rows x 16 cols bf16, 32B rows, XOR-swizzled 16B segments.
// byte offset of (row, seg) = row*32 + ((seg ^ ((row>>2)&1)) * 16)
#define TILE_B   4096               // 128*32
#define STAGE_B  16384              // Ahi,Alo,Bhi,Blo
// static shared per block: 2 * 16384 = 32768 bytes -> 2 CTAs/SM = 64KB

__device__ __forceinline__ unsigned sw_off(int row, int seg) {
    return (unsigned)(row * 32 + ((seg ^ ((row >> 2) & 1)) << 4));
}

__device__ __forceinline__ void load_tile(unsigned sm, const bf16* g, int ld,
                                          int k0, int tid) {
    int row = tid >> 1, seg = tid & 1;
    CPA16(sm + sw_off(row, seg), g + (size_t)row * ld + k0 + seg * 8);
}

// ---------------------------------------------------------------------------
// Fused split-bf16 GEMM: D = (Ahi+Alo)*(Bhi+Blo)^T (lo*lo dropped)
// CTA 128x128, K-chunk 16, 2-stage cp.async double buffer, 8 warps (2m x 4n),
// 2 CTAs per SM for latency overlap.
// ---------------------------------------------------------------------------
template<int NC, int LDA, int LDB, bool EPI1>
__global__ __launch_bounds__(256, 2) void gemm_kernel(float* __restrict__ Out,
                                                      int ldo) {
    const bf16* __restrict__ Ahi = EPI1 ? g_Qhi : g_Ghi;
    const bf16* __restrict__ Alo = EPI1 ? g_Qlo : g_Glo;
    const bf16* __restrict__ Bhi = EPI1 ? g_Khi : g_Vthi;
    const bf16* __restrict__ Blo = EPI1 ? g_Klo : g_Vtlo;

    __shared__ __align__(128) char dsm[2 * STAGE_B];   // 32768 bytes
    const unsigned sbase = smem_u32(dsm);
    const int tid = threadIdx.x, lane = tid & 31, wid = tid >> 5;
    const int wm = wid >> 2, wn = wid & 3;
    const int m0 = blockIdx.y * 128, n0 = blockIdx.x * 128;

    const bf16* pAhi = Ahi + (size_t)m0 * LDA;
    const bf16* pAlo = Alo + (size_t)m0 * LDA;
    const bf16* pBhi = Bhi + (size_t)n0 * LDB;
    const bf16* pBlo = Blo + (size_t)n0 * LDB;

    float acc[4][4][4];
#pragma unroll
    for (int f = 0; f < 4; ++f)
#pragma unroll
        for (int g = 0; g < 4; ++g)
#pragma unroll
            for (int j = 0; j < 4; ++j) acc[f][g][j] = 0.f;

    // prologue: stages 0,1 <- chunks 0,1
#pragma unroll
    for (int s = 0; s < 2; ++s) {
        unsigned sb = sbase + s * STAGE_B;
        int k0 = s * 16;
        load_tile(sb,              pAhi, LDA, k0, tid);
        load_tile(sb + TILE_B,     pAlo, LDA, k0, tid);
        load_tile(sb + 2 * TILE_B, pBhi, LDB, k0, tid);
        load_tile(sb + 3 * TILE_B, pBlo, LDB, k0, tid);
        CPCOMMIT();
    }

    // ldmatrix lane addressing (K=16: one k-step per chunk)
    const int ra = lane & 15, sa = lane >> 4;            // A x4
    const int rb = lane & 7,  sbseg = (lane >> 3) & 1;   // B x2

    for (int c = 0; c < NC; ++c) {
        CPWAIT1();
        __syncthreads();
        unsigned sb = sbase + (c & 1) * STAGE_B;
        unsigned ah[4][4], al[4][4], bh[4][2], bl[4][2];
#pragma unroll
        for (int f = 0; f < 4; ++f) {
            unsigned ad = sb + sw_off(wm * 64 + f * 16 + ra, sa);
            LDSM4(ah[f][0], ah[f][1], ah[f][2], ah[f][3], ad);
            LDSM4(al[f][0], al[f][1], al[f][2], al[f][3], ad + TILE_B);
        }
#pragma unroll
        for (int g = 0; g < 4; ++g) {
            unsigned bd = sb + 2 * TILE_B + sw_off(wn * 32 + g * 8 + rb, sbseg);
            LDSM2(bh[g][0], bh[g][1], bd);
            LDSM2(bl[g][0], bl[g][1], bd + TILE_B);
        }
#pragma unroll
        for (int f = 0; f < 4; ++f)
#pragma unroll
            for (int g = 0; g < 4; ++g) {
                MMA(acc[f][g], ah[f], bh[g]);
                MMA(acc[f][g], al[f], bh[g]);
                MMA(acc[f][g], ah[f], bl[g]);
            }
        __syncthreads();
        if (c + 2 < NC) {
            unsigned sn = sbase + (c & 1) * STAGE_B;
            int k0 = (c + 2) * 16;
            load_tile(sn,              pAhi, LDA, k0, tid);
            load_tile(sn + TILE_B,     pAlo, LDA, k0, tid);
            load_tile(sn + 2 * TILE_B, pBhi, LDB, k0, tid);
            load_tile(sn + 3 * TILE_B, pBlo, LDB, k0, tid);
        }
        CPCOMMIT();
    }

    // epilogue
    const int mrb = m0 + wm * 64 + (lane >> 2);
    const int ncb = n0 + wn * 32 + (lane & 3) * 2;
#pragma unroll
    for (int f = 0; f < 4; ++f) {
        const int r0 = mrb + f * 16;
        float s0 = 0.f, s1 = 0.f;
#pragma unroll
        for (int g = 0; g < 4; ++g) {
            const int cc = ncb + g * 8;
            if (EPI1) {
                *(float2*)&g_S[(size_t)r0 * NB + cc] =
                    make_float2(acc[f][g][0], acc[f][g][1]);
                *(float2*)&g_S[(size_t)(r0 + 8) * NB + cc] =
                    make_float2(acc[f][g][2], acc[f][g][3]);
                s0 += acc[f][g][0] * acc[f][g][0] + acc[f][g][1] * acc[f][g][1];
                s1 += acc[f][g][2] * acc[f][g][2] + acc[f][g][3] * acc[f][g][3];
            } else {
                *(float2*)&Out[(size_t)r0 * ldo + cc] =
                    make_float2(acc[f][g][0], acc[f][g][1]);
                *(float2*)&Out[(size_t)(r0 + 8) * ldo + cc] =
                    make_float2(acc[f][g][2], acc[f][g][3]);
            }
        }
        if (EPI1) {
            s0 += __shfl_xor_sync(0xffffffff, s0, 1);
            s0 += __shfl_xor_sync(0xffffffff, s0, 2);
            s1 += __shfl_xor_sync(0xffffffff, s1, 1);
            s1 += __shfl_xor_sync(0xffffffff, s1, 2);
            if ((lane & 3) == 0) {
                atomicAdd(&g_sumsq[r0], s0);
                atomicAdd(&g_sumsq[r0 + 8], s1);
            }
        }
    }
}

// ---------------- elementwise kernels --------------------------------------
__device__ __forceinline__ void split4(const float4 v, uint2& H, uint2& L) {
    union { unsigned short s[4]; uint2 u; } h, l;
    const float f[4] = {v.x, v.y, v.z, v.w};
#pragma unroll
    for (int j = 0; j < 4; ++j) {
        bf16 hb = __float2bfloat16(f[j]);
        h.s[j] = __bfloat16_as_ushort(hb);
        l.s[j] = __bfloat16_as_ushort(__float2bfloat16(f[j] - __bfloat162float(hb)));
    }
    H = h.u; L = l.u;
}

__global__ __launch_bounds__(256) void splitQK_kernel(const float* __restrict__ q,
                                                      const float* __restrict__ k) {
    size_t i = (size_t)blockIdx.x * 256 + threadIdx.x;    // over MT*DD/4
    uint2 H, L;
    split4(((const float4*)q)[i], H, L);
    ((uint2*)g_Qhi)[i] = H; ((uint2*)g_Qlo)[i] = L;
    split4(((const float4*)k)[i], H, L);
    ((uint2*)g_Khi)[i] = H; ((uint2*)g_Klo)[i] = L;
}

__global__ void vtrans_kernel(const float* __restrict__ V) {
    __shared__ float t[32][33];
    const int o0 = blockIdx.x * 32, n0 = blockIdx.y * 32;
    const int tx = threadIdx.x, ty = threadIdx.y;
    for (int r = ty; r < 32; r += 8)
        t[r][tx] = V[(size_t)(n0 + r) * DO + o0 + tx];
    __syncthreads();
    for (int r = ty; r < 32; r += 8) {
        float f = t[tx][r];
        size_t idx = (size_t)(o0 + r) * NB + n0 + tx;
        bf16 h = __float2bfloat16(f);
        g_Vthi[idx] = h;
        g_Vtlo[idx] = __float2bfloat16(f - __bfloat162float(h));
    }
}

__global__ void zero_sumsq_kernel() {
    int i = blockIdx.x * 256 + threadIdx.x;
    if (i < MT) g_sumsq[i] = 0.f;
}
__global__ void row_scale_kernel2() {
    int i = blockIdx.x * 256 + threadIdx.x;
    if (i < MT) g_scale[i] = 90.50966799187809f / sqrtf(g_sumsq[i]);
}

__global__ __launch_bounds__(256) void gating_kernel() {
    size_t i = (size_t)blockIdx.x * 256 + threadIdx.x;    // over MT*NB/8
    size_t off = i * 8;
    const float sc = g_scale[off >> 13];
    float4 v0 = *(const float4*)(g_S + off);
    float4 v1 = *(const float4*)(g_S + off + 4);
    float f[8] = {v0.x, v0.y, v0.z, v0.w, v1.x, v1.y, v1.z, v1.w};
    union { unsigned short s[8]; uint4 v; } OH, OL;
#pragma unroll
    for (int j = 0; j < 8; ++j) {
        float x = f[j] * sc;
        float g = 0.5f * x * (1.0f + erff(x * 0.70710678118654752f));
        bf16 h = __float2bfloat16(g);
        OH.s[j] = __bfloat16_as_ushort(h);
        OL.s[j] = __bfloat16_as_ushort(__float2bfloat16(g - __bfloat162float(h)));
    }
    *(uint4*)(g_Ghi + off) = OH.v;
    *(uint4*)(g_Glo + off) = OL.v;
}

// ---------------------------------------------------------------------------
extern "C" void kernel_launch(void* const* d_in, const int* in_sizes, int n_in,
                              void* d_out, int out_size) {
    const float* q = (const float*)d_in[0];
    const float* k = (const float*)d_in[1];
    const float* v = (const float*)d_in[2];
    float* o = (float*)d_out;

    splitQK_kernel<<<(MT * DD / 4) / 256, 256>>>(q, k);
    vtrans_kernel<<<dim3(DO / 32, NB / 32), dim3(32, 8)>>>(v);
    zero_sumsq_kernel<<<MT / 256, 256>>>();
    gemm_kernel<DD / 16, DD, DD, true><<<dim3(NB / 128, MT / 128), 256>>>(
        nullptr, NB);
    row_scale_kernel2<<<MT / 256, 256>>>();
    gating_kernel<<<(int)((size_t)MT * NB / 8 / 256), 256>>>();
    gemm_kernel<NB / 16, NB, NB, false><<<dim3(DO / 128, MT / 128), 256>>>(
        o, DO);
}